// round 8
// baseline (speedup 1.0000x reference)
#include <cuda_runtime.h>
#include <cuda_fp16.h>
#include <cstdint>

// Problem constants
#define N_V   50000
#define R_    5
#define A_    8
#define RA    40
#define C_    64
#define KX    2560            // RA * C
#define KTOT  2624            // KX + C (center fold appended)
#define NCOL  512             // O * T
#define KT_N  82              // KTOT / 32
#define MB_N  391             // ceil(50048 / 128)

// Scratch (static device arrays — no cudaMalloc allowed)
// A in fp16 MMA-fragment layout: per (mb of 128 rows, kt of 32 k): 4096 halves (8KB).
__device__ __half g_Afrag[(size_t)MB_N * KT_N * 4096];   // ~256 MB
// B in fp16 MMA-fragment layout: per (nb of 128 cols, kt): 4096 halves.
__device__ __half g_Bfrag[(size_t)4 * KT_N * 4096];      // 2.7 MB
__device__ float g_biasExt[NCOL];

__device__ __forceinline__ uint32_t smem_u32(const void* p) {
    uint32_t a;
    asm("{ .reg .u64 t; cvta.to.shared.u64 t, %1; cvt.u32.u64 %0, t; }" : "=r"(a) : "l"(p));
    return a;
}

// ---------------------------------------------------------------------------
// K0: fold interpolation prior + rotation + center weights into B-fragments.
//   Weff[o,t,m,c] = sum_{r,a} coeff[r,a,m] * W[t, r, (a+o)%A, c]
// f16 m16n8k16 B fragment: thread(g=ln>>2,t4=ln&3): b0={B[k0][col],B[k0+1][col]},
// b1={B[k0+8],B[k0+9]}, k0 = kk*16 + t4*2, col = NT*8 + g.
// half-index in (nb,kt) chunk: ((NT*2+kk)*32 + ln)*4 + r*2 + e
// ---------------------------------------------------------------------------
__device__ __forceinline__ size_t bfrag_addr(int k, int j) {
    int kt = k >> 5, kl = k & 31;
    int kk = kl >> 4, kb = kl & 15;
    int r = kb >> 3, rem = kb & 7, t4 = rem >> 1, e = rem & 1;
    int nb = j >> 7, nl = j & 127;
    int NT = nl >> 3, gn = nl & 7;
    int ln = gn * 4 + t4;
    return ((size_t)(nb * KT_N + kt)) * 4096 +
           (size_t)(((NT * 2 + kk) * 32 + ln) * 4 + r * 2 + e);
}

__global__ void build_B_kernel(const float* __restrict__ nw,
                               const float* __restrict__ cw,
                               const float* __restrict__ bias,
                               const float* __restrict__ coeff)
{
    int j = blockIdx.x;            // 0..511
    int o = j >> 6;
    int t = j & 63;
    int c = threadIdx.x;           // 64 threads

    __shared__ float s_coeff[R_ * A_ * RA];
    for (int i = c; i < R_ * A_ * RA; i += 64) s_coeff[i] = coeff[i];
    __syncthreads();

    float wv[R_][A_];
    #pragma unroll
    for (int r = 0; r < R_; r++)
        #pragma unroll
        for (int a = 0; a < A_; a++)
            wv[r][a] = nw[(((size_t)t * R_ + r) * A_ + ((a + o) & 7)) * C_ + c];

    for (int m = 0; m < RA; m++) {
        float acc = 0.f;
        #pragma unroll
        for (int r = 0; r < R_; r++)
            #pragma unroll
            for (int a = 0; a < A_; a++)
                acc += s_coeff[(r * A_ + a) * RA + m] * wv[r][a];
        g_Bfrag[bfrag_addr(m * C_ + c, j)] = __float2half_rn(acc);
    }
    g_Bfrag[bfrag_addr(KX + c, j)] = __float2half_rn(cw[t * C_ + c]);
    if (c == 0) g_biasExt[j] = bias[t];
}

// ---------------------------------------------------------------------------
// K1: barycentric gather + interpolation -> fp16 A-fragments.
// One block per vertex PAIR (n, n+8). Lane=channel coalesced gathers.
// A fragment uint4 at ((MT*2+kk)*32 + gl*4 + t4):
//   x={s0[k0],s0[k0+1]}, y={s1[k0],s1[k0+1]}, z={s0[k0+8],s0[k0+9]},
//   w={s1[k0+8],s1[k0+9]},  k0 = kt*32 + kk*16 + t4*2
// ---------------------------------------------------------------------------
__global__ __launch_bounds__(256)
void build_X_kernel(const float* __restrict__ ms,
                    const float* __restrict__ bary)
{
    int bp = blockIdx.x;
    int mb = bp >> 6;
    int q  = bp & 63;
    int MT = q >> 3;
    int gl = q & 7;
    int n0 = mb * 128 + MT * 16 + gl;

    __shared__ float s_row[2][KTOT];
    __shared__ float sb[240];
    int tid = threadIdx.x;

    #pragma unroll
    for (int v = 0; v < 2; v++) {
        int n = n0 + 8 * v;
        if (n < N_V) {
            if (tid < 240) sb[tid] = bary[(size_t)n * 240 + tid];
            __syncthreads();
            int g4 = tid >> 6;
            int c  = tid & 63;
            #pragma unroll
            for (int it = 0; it < 10; it++) {
                int m  = it * 4 + g4;
                int i0 = (int)sb[m * 6 + 0]; float w0 = sb[m * 6 + 1];
                int i1 = (int)sb[m * 6 + 2]; float w1 = sb[m * 6 + 3];
                int i2 = (int)sb[m * 6 + 4]; float w2 = sb[m * 6 + 5];
                s_row[v][m * C_ + c] = w0 * ms[(size_t)i0 * C_ + c]
                                     + w1 * ms[(size_t)i1 * C_ + c]
                                     + w2 * ms[(size_t)i2 * C_ + c];
            }
            if (g4 == 0) s_row[v][KX + c] = ms[(size_t)n * C_ + c];
        } else {
            for (int i = tid; i < KTOT; i += 256) s_row[v][i] = 0.f;
        }
        __syncthreads();
    }

    // 82 kt x 2 kk x 4 t4 = 656 uint4 per pair
    for (int w = tid; w < KT_N * 8; w += 256) {
        int kt = w >> 3;
        int kk = (w >> 2) & 1;
        int t4 = w & 3;
        int k0 = kt * 32 + kk * 16 + t4 * 2;
        __half2 x = __floats2half2_rn(s_row[0][k0],     s_row[0][k0 + 1]);
        __half2 y = __floats2half2_rn(s_row[1][k0],     s_row[1][k0 + 1]);
        __half2 z = __floats2half2_rn(s_row[0][k0 + 8], s_row[0][k0 + 9]);
        __half2 u = __floats2half2_rn(s_row[1][k0 + 8], s_row[1][k0 + 9]);
        uint4 val;
        val.x = *(uint32_t*)&x; val.y = *(uint32_t*)&y;
        val.z = *(uint32_t*)&z; val.w = *(uint32_t*)&u;
        ((uint4*)(g_Afrag + ((size_t)mb * KT_N + kt) * 4096))
            [(MT * 2 + kk) * 32 + gl * 4 + t4] = val;
    }
}

// ---------------------------------------------------------------------------
// K2: fp16 mma.sync m16n8k16 GEMM + bias + relu.
// BM=128, BN=256, BK=32. 256 threads = 8 warps (2m x 4n), warp tile 64x64.
// 4-stage cp.async pipeline (24KB/stage = A 8KB + B0 8KB + B1 8KB).
// ---------------------------------------------------------------------------
__device__ __forceinline__ void mma_f16(float* c, uint32_t a0, uint32_t a1,
                                        uint32_t a2, uint32_t a3,
                                        uint32_t b0, uint32_t b1)
{
    asm volatile(
        "mma.sync.aligned.m16n8k16.row.col.f32.f16.f16.f32 "
        "{%0,%1,%2,%3}, {%4,%5,%6,%7}, {%8,%9}, {%0,%1,%2,%3};\n"
        : "+f"(c[0]), "+f"(c[1]), "+f"(c[2]), "+f"(c[3])
        : "r"(a0), "r"(a1), "r"(a2), "r"(a3), "r"(b0), "r"(b1));
}
__device__ __forceinline__ void cp16(uint32_t s, const void* g) {
    asm volatile("cp.async.cg.shared.global [%0], [%1], 16;" :: "r"(s), "l"(g));
}

#define STAGE_BYTES 24576
#define NSTAGE      4
#define SMEM_TOTAL  (NSTAGE * STAGE_BYTES)   // 96KB

__global__ __launch_bounds__(256, 1)
void gemm_relu_kernel(float* __restrict__ out)
{
    extern __shared__ char smem[];
    uint32_t sbase = smem_u32(smem);

    int tid  = threadIdx.x;
    int warp = tid >> 5;
    int ln   = tid & 31;
    int wm   = warp >> 2;          // 0..1  (m half, 64 rows)
    int wn   = warp & 3;           // 0..3  (n quarter, 64 cols)
    int mb   = blockIdx.y;
    int bx   = blockIdx.x;         // 0..1  (n half of 256)

    const uint4* Ag  = (const uint4*)(g_Afrag + (size_t)mb * KT_N * 4096);
    const uint4* Bg0 = (const uint4*)(g_Bfrag + (size_t)(bx * 2 + 0) * KT_N * 4096);
    const uint4* Bg1 = (const uint4*)(g_Bfrag + (size_t)(bx * 2 + 1) * KT_N * 4096);

    auto issue = [&](int s) {
        uint32_t dst = sbase + (uint32_t)(s & (NSTAGE - 1)) * STAGE_BYTES;
        const uint4* As = Ag + (size_t)s * 512;
        cp16(dst + tid * 16, As + tid);
        cp16(dst + (tid + 256) * 16, As + tid + 256);
        const uint4* Bs0 = Bg0 + (size_t)s * 512;
        cp16(dst + 8192 + tid * 16, Bs0 + tid);
        cp16(dst + 8192 + (tid + 256) * 16, Bs0 + tid + 256);
        const uint4* Bs1 = Bg1 + (size_t)s * 512;
        cp16(dst + 16384 + tid * 16, Bs1 + tid);
        cp16(dst + 16384 + (tid + 256) * 16, Bs1 + tid + 256);
    };

    issue(0);
    asm volatile("cp.async.commit_group;" ::: "memory");
    issue(1);
    asm volatile("cp.async.commit_group;" ::: "memory");
    issue(2);
    asm volatile("cp.async.commit_group;" ::: "memory");

    float acc[4][8][4];
    #pragma unroll
    for (int mt = 0; mt < 4; mt++)
        #pragma unroll
        for (int nt = 0; nt < 8; nt++)
            #pragma unroll
            for (int i = 0; i < 4; i++) acc[mt][nt][i] = 0.f;

    for (int kt = 0; kt < KT_N; kt++) {
        asm volatile("cp.async.wait_group 2;" ::: "memory");
        __syncthreads();

        if (kt + 3 < KT_N) issue(kt + 3);
        asm volatile("cp.async.commit_group;" ::: "memory");

        uint32_t bufA = sbase + (uint32_t)(kt & (NSTAGE - 1)) * STAGE_BYTES;
        uint32_t bufB = bufA + 8192 + (uint32_t)(wn >> 1) * 8192;

        #pragma unroll
        for (int kk = 0; kk < 2; kk++) {
            uint4 af[4];
            uint2 bf[8];
            #pragma unroll
            for (int mt = 0; mt < 4; mt++) {
                uint32_t a = bufA + ((((wm * 4 + mt) * 2 + kk) * 32 + ln) * 16);
                asm volatile("ld.shared.v4.b32 {%0,%1,%2,%3}, [%4];"
                             : "=r"(af[mt].x), "=r"(af[mt].y), "=r"(af[mt].z), "=r"(af[mt].w)
                             : "r"(a));
            }
            #pragma unroll
            for (int nt = 0; nt < 8; nt++) {
                int NT = (wn & 1) * 8 + nt;
                uint32_t b = bufB + (((NT * 2 + kk) * 32 + ln) * 8);
                asm volatile("ld.shared.v2.b32 {%0,%1}, [%2];"
                             : "=r"(bf[nt].x), "=r"(bf[nt].y) : "r"(b));
            }
            #pragma unroll
            for (int mt = 0; mt < 4; mt++)
                #pragma unroll
                for (int nt = 0; nt < 8; nt++)
                    mma_f16(acc[mt][nt], af[mt].x, af[mt].y, af[mt].z, af[mt].w,
                            bf[nt].x, bf[nt].y);
        }
        __syncthreads();
    }

    // epilogue: bias + relu
    int g  = ln >> 2;
    int t4 = ln & 3;
    #pragma unroll
    for (int nt = 0; nt < 8; nt++) {
        int col = bx * 256 + wn * 64 + nt * 8 + t4 * 2;
        float b0 = g_biasExt[col];
        float b1 = g_biasExt[col + 1];
        #pragma unroll
        for (int mt = 0; mt < 4; mt++) {
            int row0 = mb * 128 + wm * 64 + mt * 16 + g;
            float v0 = acc[mt][nt][0] + b0;
            float v1 = acc[mt][nt][1] + b1;
            float v2 = acc[mt][nt][2] + b0;
            float v3 = acc[mt][nt][3] + b1;
            v0 = v0 > 0.f ? v0 : 0.f;
            v1 = v1 > 0.f ? v1 : 0.f;
            v2 = v2 > 0.f ? v2 : 0.f;
            v3 = v3 > 0.f ? v3 : 0.f;
            if (row0 < N_V)
                *(float2*)(out + (size_t)row0 * NCOL + col) = make_float2(v0, v1);
            if (row0 + 8 < N_V)
                *(float2*)(out + (size_t)(row0 + 8) * NCOL + col) = make_float2(v2, v3);
        }
    }
}

// ---------------------------------------------------------------------------
// Launch
// Inputs: mesh_signal, bary_coordinates, neighbor_weights, center_weights,
//         bias, interp_coeff
// ---------------------------------------------------------------------------
extern "C" void kernel_launch(void* const* d_in, const int* in_sizes, int n_in,
                              void* d_out, int out_size)
{
    const float* ms    = (const float*)d_in[0];
    const float* bary  = (const float*)d_in[1];
    const float* nw    = (const float*)d_in[2];
    const float* cw    = (const float*)d_in[3];
    const float* bias  = (const float*)d_in[4];
    const float* coeff = (const float*)d_in[5];
    float* out = (float*)d_out;

    cudaFuncSetAttribute(gemm_relu_kernel,
                         cudaFuncAttributeMaxDynamicSharedMemorySize, SMEM_TOTAL);

    build_B_kernel<<<NCOL, 64>>>(nw, cw, bias, coeff);
    build_X_kernel<<<MB_N * 64, 256>>>(ms, bary);

    dim3 grid(2, MB_N);
    gemm_relu_kernel<<<grid, 256, SMEM_TOTAL>>>(out);
}

// round 9
// speedup vs baseline: 1.5307x; 1.5307x over previous
#include <cuda_runtime.h>
#include <cuda_fp16.h>
#include <cstdint>

// Problem constants
#define N_V   50000
#define R_    5
#define A_    8
#define RA    40
#define C_    64
#define KX    2560            // RA * C
#define KTOT  2624            // KX + C (center fold appended)
#define NCOL  512             // O * T
#define KT_N  82              // KTOT / 32
#define MB_N  391             // ceil(50048 / 128)

// Scratch (static device arrays — no cudaMalloc allowed)
__device__ __half g_Afrag[(size_t)MB_N * KT_N * 4096];   // ~256 MB
__device__ __half g_Bfrag[(size_t)4 * KT_N * 4096];      // 2.7 MB
__device__ float g_biasExt[NCOL];

__device__ __forceinline__ uint32_t smem_u32(const void* p) {
    uint32_t a;
    asm("{ .reg .u64 t; cvta.to.shared.u64 t, %1; cvt.u32.u64 %0, t; }" : "=r"(a) : "l"(p));
    return a;
}

// Dummy kernel: shifts ncu's capture window (-s 5 -c 1) onto the GEMM.
__global__ void dummy_kernel() {}

// ---------------------------------------------------------------------------
// K0: fold interpolation prior + rotation + center weights into B-fragments.
// f16 m16n8k16 B fragment half-index in (nb,kt) chunk:
//   ((NT*2+kk)*32 + ln)*4 + r*2 + e
// ---------------------------------------------------------------------------
__device__ __forceinline__ size_t bfrag_addr(int k, int j) {
    int kt = k >> 5, kl = k & 31;
    int kk = kl >> 4, kb = kl & 15;
    int r = kb >> 3, rem = kb & 7, t4 = rem >> 1, e = rem & 1;
    int nb = j >> 7, nl = j & 127;
    int NT = nl >> 3, gn = nl & 7;
    int ln = gn * 4 + t4;
    return ((size_t)(nb * KT_N + kt)) * 4096 +
           (size_t)(((NT * 2 + kk) * 32 + ln) * 4 + r * 2 + e);
}

__global__ void build_B_kernel(const float* __restrict__ nw,
                               const float* __restrict__ cw,
                               const float* __restrict__ bias,
                               const float* __restrict__ coeff)
{
    int j = blockIdx.x;            // 0..511
    int o = j >> 6;
    int t = j & 63;
    int c = threadIdx.x;           // 64 threads

    __shared__ float s_coeff[R_ * A_ * RA];
    for (int i = c; i < R_ * A_ * RA; i += 64) s_coeff[i] = coeff[i];
    __syncthreads();

    float wv[R_][A_];
    #pragma unroll
    for (int r = 0; r < R_; r++)
        #pragma unroll
        for (int a = 0; a < A_; a++)
            wv[r][a] = nw[(((size_t)t * R_ + r) * A_ + ((a + o) & 7)) * C_ + c];

    for (int m = 0; m < RA; m++) {
        float acc = 0.f;
        #pragma unroll
        for (int r = 0; r < R_; r++)
            #pragma unroll
            for (int a = 0; a < A_; a++)
                acc += s_coeff[(r * A_ + a) * RA + m] * wv[r][a];
        g_Bfrag[bfrag_addr(m * C_ + c, j)] = __float2half_rn(acc);
    }
    g_Bfrag[bfrag_addr(KX + c, j)] = __float2half_rn(cw[t * C_ + c]);
    if (c == 0) g_biasExt[j] = bias[t];
}

// ---------------------------------------------------------------------------
// K1: barycentric gather + interpolation -> fp16 A-fragments.
// One block per vertex PAIR (n, n+8), 512 threads: tid bit 8 selects the
// vertex, both processed concurrently; ONE sync before fragment writes.
// ---------------------------------------------------------------------------
__global__ __launch_bounds__(512)
void build_X_kernel(const float* __restrict__ ms,
                    const float* __restrict__ bary)
{
    int bp = blockIdx.x;
    int mb = bp >> 6;
    int q  = bp & 63;
    int MT = q >> 3;
    int gl = q & 7;
    int n0 = mb * 128 + MT * 16 + gl;

    __shared__ float s_row[2][KTOT];
    __shared__ float sb[2][240];
    int tid = threadIdx.x;
    int v   = tid >> 8;            // 0..1 vertex select
    int t   = tid & 255;
    int n   = n0 + 8 * v;

    if (n < N_V) {
        if (t < 240) sb[v][t] = bary[(size_t)n * 240 + t];
    } else {
        if (t < 240) sb[v][t] = 0.f;
    }
    __syncthreads();

    if (n < N_V) {
        int g4 = t >> 6;           // 0..3
        int c  = t & 63;
        #pragma unroll
        for (int it = 0; it < 10; it++) {
            int m  = it * 4 + g4;
            int i0 = (int)sb[v][m * 6 + 0]; float w0 = sb[v][m * 6 + 1];
            int i1 = (int)sb[v][m * 6 + 2]; float w1 = sb[v][m * 6 + 3];
            int i2 = (int)sb[v][m * 6 + 4]; float w2 = sb[v][m * 6 + 5];
            s_row[v][m * C_ + c] = w0 * ms[(size_t)i0 * C_ + c]
                                 + w1 * ms[(size_t)i1 * C_ + c]
                                 + w2 * ms[(size_t)i2 * C_ + c];
        }
        if (g4 == 0) s_row[v][KX + c] = ms[(size_t)n * C_ + c];
    } else {
        for (int i = t; i < KTOT; i += 256) s_row[v][i] = 0.f;
    }
    __syncthreads();

    // 656 uint4 fragment writes, 512 threads
    for (int w = tid; w < KT_N * 8; w += 512) {
        int kt = w >> 3;
        int kk = (w >> 2) & 1;
        int t4 = w & 3;
        int k0 = kt * 32 + kk * 16 + t4 * 2;
        __half2 x = __floats2half2_rn(s_row[0][k0],     s_row[0][k0 + 1]);
        __half2 y = __floats2half2_rn(s_row[1][k0],     s_row[1][k0 + 1]);
        __half2 z = __floats2half2_rn(s_row[0][k0 + 8], s_row[0][k0 + 9]);
        __half2 u = __floats2half2_rn(s_row[1][k0 + 8], s_row[1][k0 + 9]);
        uint4 val;
        val.x = *(uint32_t*)&x; val.y = *(uint32_t*)&y;
        val.z = *(uint32_t*)&z; val.w = *(uint32_t*)&u;
        ((uint4*)(g_Afrag + ((size_t)mb * KT_N + kt) * 4096))
            [(MT * 2 + kk) * 32 + gl * 4 + t4] = val;
    }
}

// ---------------------------------------------------------------------------
// K2: fp16 mma.sync m16n8k16 GEMM + bias + relu.
// BM=128, BN=256, BK=32. 256 threads = 8 warps (2m x 4n), warp tile 64x64.
// 4-stage cp.async pipeline (24KB/stage).
// ---------------------------------------------------------------------------
__device__ __forceinline__ void mma_f16(float* c, uint32_t a0, uint32_t a1,
                                        uint32_t a2, uint32_t a3,
                                        uint32_t b0, uint32_t b1)
{
    asm volatile(
        "mma.sync.aligned.m16n8k16.row.col.f32.f16.f16.f32 "
        "{%0,%1,%2,%3}, {%4,%5,%6,%7}, {%8,%9}, {%0,%1,%2,%3};\n"
        : "+f"(c[0]), "+f"(c[1]), "+f"(c[2]), "+f"(c[3])
        : "r"(a0), "r"(a1), "r"(a2), "r"(a3), "r"(b0), "r"(b1));
}
__device__ __forceinline__ void cp16(uint32_t s, const void* g) {
    asm volatile("cp.async.cg.shared.global [%0], [%1], 16;" :: "r"(s), "l"(g));
}

#define STAGE_BYTES 24576
#define NSTAGE      4
#define SMEM_TOTAL  (NSTAGE * STAGE_BYTES)   // 96KB

__global__ __launch_bounds__(256, 1)
void gemm_relu_kernel(float* __restrict__ out)
{
    extern __shared__ char smem[];
    uint32_t sbase = smem_u32(smem);

    int tid  = threadIdx.x;
    int warp = tid >> 5;
    int ln   = tid & 31;
    int wm   = warp >> 2;          // 0..1  (m half, 64 rows)
    int wn   = warp & 3;           // 0..3  (n quarter, 64 cols)
    int mb   = blockIdx.y;
    int bx   = blockIdx.x;         // 0..1  (n half of 256)

    const uint4* Ag  = (const uint4*)(g_Afrag + (size_t)mb * KT_N * 4096);
    const uint4* Bg0 = (const uint4*)(g_Bfrag + (size_t)(bx * 2 + 0) * KT_N * 4096);
    const uint4* Bg1 = (const uint4*)(g_Bfrag + (size_t)(bx * 2 + 1) * KT_N * 4096);

    auto issue = [&](int s) {
        uint32_t dst = sbase + (uint32_t)(s & (NSTAGE - 1)) * STAGE_BYTES;
        const uint4* As = Ag + (size_t)s * 512;
        cp16(dst + tid * 16, As + tid);
        cp16(dst + (tid + 256) * 16, As + tid + 256);
        const uint4* Bs0 = Bg0 + (size_t)s * 512;
        cp16(dst + 8192 + tid * 16, Bs0 + tid);
        cp16(dst + 8192 + (tid + 256) * 16, Bs0 + tid + 256);
        const uint4* Bs1 = Bg1 + (size_t)s * 512;
        cp16(dst + 16384 + tid * 16, Bs1 + tid);
        cp16(dst + 16384 + (tid + 256) * 16, Bs1 + tid + 256);
    };

    issue(0);
    asm volatile("cp.async.commit_group;" ::: "memory");
    issue(1);
    asm volatile("cp.async.commit_group;" ::: "memory");
    issue(2);
    asm volatile("cp.async.commit_group;" ::: "memory");

    float acc[4][8][4];
    #pragma unroll
    for (int mt = 0; mt < 4; mt++)
        #pragma unroll
        for (int nt = 0; nt < 8; nt++)
            #pragma unroll
            for (int i = 0; i < 4; i++) acc[mt][nt][i] = 0.f;

    for (int kt = 0; kt < KT_N; kt++) {
        asm volatile("cp.async.wait_group 2;" ::: "memory");
        __syncthreads();

        if (kt + 3 < KT_N) issue(kt + 3);
        asm volatile("cp.async.commit_group;" ::: "memory");

        uint32_t bufA = sbase + (uint32_t)(kt & (NSTAGE - 1)) * STAGE_BYTES;
        uint32_t bufB = bufA + 8192 + (uint32_t)(wn >> 1) * 8192;

        #pragma unroll
        for (int kk = 0; kk < 2; kk++) {
            uint4 af[4];
            uint2 bf[8];
            #pragma unroll
            for (int mt = 0; mt < 4; mt++) {
                uint32_t a = bufA + ((((wm * 4 + mt) * 2 + kk) * 32 + ln) * 16);
                asm volatile("ld.shared.v4.b32 {%0,%1,%2,%3}, [%4];"
                             : "=r"(af[mt].x), "=r"(af[mt].y), "=r"(af[mt].z), "=r"(af[mt].w)
                             : "r"(a));
            }
            #pragma unroll
            for (int nt = 0; nt < 8; nt++) {
                int NT = (wn & 1) * 8 + nt;
                uint32_t b = bufB + (((NT * 2 + kk) * 32 + ln) * 8);
                asm volatile("ld.shared.v2.b32 {%0,%1}, [%2];"
                             : "=r"(bf[nt].x), "=r"(bf[nt].y) : "r"(b));
            }
            #pragma unroll
            for (int mt = 0; mt < 4; mt++)
                #pragma unroll
                for (int nt = 0; nt < 8; nt++)
                    mma_f16(acc[mt][nt], af[mt].x, af[mt].y, af[mt].z, af[mt].w,
                            bf[nt].x, bf[nt].y);
        }
        __syncthreads();
    }

    // epilogue: bias + relu
    int g  = ln >> 2;
    int t4 = ln & 3;
    #pragma unroll
    for (int nt = 0; nt < 8; nt++) {
        int col = bx * 256 + wn * 64 + nt * 8 + t4 * 2;
        float b0 = g_biasExt[col];
        float b1 = g_biasExt[col + 1];
        #pragma unroll
        for (int mt = 0; mt < 4; mt++) {
            int row0 = mb * 128 + wm * 64 + mt * 16 + g;
            float v0 = acc[mt][nt][0] + b0;
            float v1 = acc[mt][nt][1] + b1;
            float v2 = acc[mt][nt][2] + b0;
            float v3 = acc[mt][nt][3] + b1;
            v0 = v0 > 0.f ? v0 : 0.f;
            v1 = v1 > 0.f ? v1 : 0.f;
            v2 = v2 > 0.f ? v2 : 0.f;
            v3 = v3 > 0.f ? v3 : 0.f;
            if (row0 < N_V)
                *(float2*)(out + (size_t)row0 * NCOL + col) = make_float2(v0, v1);
            if (row0 + 8 < N_V)
                *(float2*)(out + (size_t)(row0 + 8) * NCOL + col) = make_float2(v2, v3);
        }
    }
}

// ---------------------------------------------------------------------------
// Launch. 3 dummy launches first so ncu (-s 5 -c 1) captures the GEMM
// (launch #6) instead of build_B.
// Inputs: mesh_signal, bary_coordinates, neighbor_weights, center_weights,
//         bias, interp_coeff
// ---------------------------------------------------------------------------
extern "C" void kernel_launch(void* const* d_in, const int* in_sizes, int n_in,
                              void* d_out, int out_size)
{
    const float* ms    = (const float*)d_in[0];
    const float* bary  = (const float*)d_in[1];
    const float* nw    = (const float*)d_in[2];
    const float* cw    = (const float*)d_in[3];
    const float* bias  = (const float*)d_in[4];
    const float* coeff = (const float*)d_in[5];
    float* out = (float*)d_out;

    cudaFuncSetAttribute(gemm_relu_kernel,
                         cudaFuncAttributeMaxDynamicSharedMemorySize, SMEM_TOTAL);

    dummy_kernel<<<1, 1>>>();
    dummy_kernel<<<1, 1>>>();
    dummy_kernel<<<1, 1>>>();

    build_B_kernel<<<NCOL, 64>>>(nw, cw, bias, coeff);
    build_X_kernel<<<MB_N * 64, 512>>>(ms, bary);

    dim3 grid(2, MB_N);
    gemm_relu_kernel<<<grid, 256, SMEM_TOTAL>>>(out);
}

// round 10
// speedup vs baseline: 2.5434x; 1.6616x over previous
#include <cuda_runtime.h>
#include <cuda_fp16.h>
#include <cstdint>

// Problem constants
#define N_V   50000
#define R_    5
#define A_    8
#define RA    40
#define C_    64
#define NCOL  512
#define CH_N  82              // 32-k chunks total: g0:22 (K=704), g1-3:20 (K=640)
#define MB_N  391             // ceil(50048/128)
#define SQ2   0.70710678118654752f

// Scratch (static device arrays — no cudaMalloc allowed)
// Freq-domain A panels, fp16 m16n8k16 fragment layout, per (mb, chunk).
__device__ __half g_Afrag[(size_t)MB_N * CH_N * 4096];   // ~262 MB
__device__ __half g_Bfrag[(size_t)CH_N * 4096];          // 672 KB
__device__ float  g_P[(size_t)MB_N * 128 * 512];         // ~102 MB partial products

__device__ __forceinline__ uint32_t smem_u32(const void* p) {
    uint32_t a;
    asm("{ .reg .u64 t; cvta.to.shared.u64 t, %1; cvt.u32.u64 %0, t; }" : "=r"(a) : "l"(p));
    return a;
}
__device__ __forceinline__ int grp_cb(int g) { return g == 0 ? 0 : 2 + g * 20; }

// Dummy kernel: shifts ncu capture (-s 5 -c 1) onto the GEMM (harness has 2
// launches before ours; gemm must be our 4th launch).
__global__ void dummy_kernel() {}

// 8-point real FFT, e^{-i2*pi*f*a/8} convention. out: r0,r4,r1,i1,r2,i2,r3,i3
__device__ __forceinline__ void fft8(float x0, float x1, float x2, float x3,
                                     float x4, float x5, float x6, float x7,
                                     float* o)
{
    float a04 = x0 + x4, s04 = x0 - x4;
    float a26 = x2 + x6, s26 = x2 - x6;
    float a15 = x1 + x5, s15 = x1 - x5;
    float a37 = x3 + x7, s37 = x3 - x7;
    o[0] = a04 + a26 + a15 + a37;          // r0
    o[1] = a04 + a26 - a15 - a37;          // r4
    float u = SQ2 * (s15 - s37);
    float w = SQ2 * (s15 + s37);
    o[2] = s04 + u;                        // r1
    o[3] = -(w + s26);                     // i1
    o[4] = a04 - a26;                      // r2
    o[5] = -(a15 - a37);                   // i2
    o[6] = s04 - u;                        // r3
    o[7] = -(w - s26);                     // i3
}

// B fragment half index: group chunk base cb, k within group panel, col j in [0,128)
__device__ __forceinline__ size_t bfrag_idx(int cb, int klocal, int j) {
    int kt = klocal >> 5, kl = klocal & 31;
    int kk = kl >> 4, kb = kl & 15;
    int r = kb >> 3, rem = kb & 7, t4 = rem >> 1, e = rem & 1;
    int NT = j >> 3, gn = j & 7;
    int ln = gn * 4 + t4;
    return (size_t)(cb + kt) * 4096 + (size_t)(((NT * 2 + kk) * 32 + ln) * 4 + r * 2 + e);
}

// ---------------------------------------------------------------------------
// K0: fold prior into V[t,rho,alpha,c] (= Weff at o=0), rFFT over alpha,
// write frequency-domain B fragments + center weights (x8).
// Columns per group: j=t -> "R" column, j=64+t -> "I" (or f4) column.
// ---------------------------------------------------------------------------
__global__ void build_V_kernel(const float* __restrict__ nw,
                               const float* __restrict__ cw,
                               const float* __restrict__ coeff)
{
    int t = blockIdx.x;            // 0..63 template
    int c = threadIdx.x;           // 0..63 channel

    __shared__ float s_coeff[R_ * A_ * RA];
    for (int i = c; i < R_ * A_ * RA; i += 64) s_coeff[i] = coeff[i];
    __syncthreads();

    float wv[R_][A_];
    #pragma unroll
    for (int r = 0; r < R_; r++)
        #pragma unroll
        for (int a = 0; a < A_; a++)
            wv[r][a] = nw[(((size_t)t * R_ + r) * A_ + a) * C_ + c];

    float v[RA];
    for (int m = 0; m < RA; m++) {
        float acc = 0.f;
        #pragma unroll
        for (int r = 0; r < R_; r++)
            #pragma unroll
            for (int a = 0; a < A_; a++)
                acc += s_coeff[(r * A_ + a) * RA + m] * wv[r][a];
        v[m] = acc;
    }

    #pragma unroll
    for (int rho = 0; rho < R_; rho++) {
        float o[8];
        fft8(v[rho * 8 + 0], v[rho * 8 + 1], v[rho * 8 + 2], v[rho * 8 + 3],
             v[rho * 8 + 4], v[rho * 8 + 5], v[rho * 8 + 6], v[rho * 8 + 7], o);
        int kb = rho * 64 + c;
        __half zero = __float2half_rn(0.f);
        // group 0: cols [j=t] = f0 column, [j=64+t] = f4 column
        g_Bfrag[bfrag_idx(0, kb,       t     )] = __float2half_rn(o[0]);
        g_Bfrag[bfrag_idx(0, 320 + kb, t     )] = zero;
        g_Bfrag[bfrag_idx(0, kb,       64 + t)] = zero;
        g_Bfrag[bfrag_idx(0, 320 + kb, 64 + t)] = __float2half_rn(o[1]);
        // groups 1..3: col t = R-col (Vr;Vi), col 64+t = I-col (Vi;-Vr)
        #pragma unroll
        for (int f = 1; f <= 3; f++) {
            float vr = o[f * 2], vi = o[f * 2 + 1];
            int cb = grp_cb(f);
            g_Bfrag[bfrag_idx(cb, kb,       t     )] = __float2half_rn(vr);
            g_Bfrag[bfrag_idx(cb, 320 + kb, t     )] = __float2half_rn(vi);
            g_Bfrag[bfrag_idx(cb, kb,       64 + t)] = __float2half_rn(vi);
            g_Bfrag[bfrag_idx(cb, 320 + kb, 64 + t)] = __float2half_rn(-vr);
        }
    }
    // center fold: rows [640,704) of group 0, scaled x8 (combine divides by 8)
    g_Bfrag[bfrag_idx(0, 640 + c, t     )] = __float2half_rn(8.f * cw[t * C_ + c]);
    g_Bfrag[bfrag_idx(0, 640 + c, 64 + t)] = __float2half_rn(0.f);
}

// ---------------------------------------------------------------------------
// K1: barycentric gather -> in-place angular rFFT -> fp16 A-fragments.
// One block per vertex PAIR (n, n+8), 512 threads (bit 8 = vertex).
// s_row layout after FFT: [g0: Xr0(320) Xr4(320) center(64)][g1: Xr1 Xi1]
// [g2: Xr2 Xi2][g3: Xr3 Xi3]  => 2624 floats, group chunk-aligned.
// ---------------------------------------------------------------------------
__global__ __launch_bounds__(512)
void build_X_kernel(const float* __restrict__ ms,
                    const float* __restrict__ bary)
{
    int bp = blockIdx.x;
    int mb = bp >> 6;
    int q  = bp & 63;
    int MT = q >> 3;
    int gl = q & 7;
    int n0 = mb * 128 + MT * 16 + gl;

    __shared__ float s_row[2][2624];
    __shared__ float sb[2][240];
    int tid = threadIdx.x;
    int v   = tid >> 8;
    int t   = tid & 255;
    int n   = n0 + 8 * v;

    if (t < 240) sb[v][t] = (n < N_V) ? bary[(size_t)n * 240 + t] : 0.f;
    __syncthreads();

    if (n < N_V) {
        int g4 = t >> 6;
        int c  = t & 63;
        #pragma unroll
        for (int it = 0; it < 10; it++) {
            int m  = it * 4 + g4;
            int i0 = (int)sb[v][m * 6 + 0]; float w0 = sb[v][m * 6 + 1];
            int i1 = (int)sb[v][m * 6 + 2]; float w1 = sb[v][m * 6 + 3];
            int i2 = (int)sb[v][m * 6 + 4]; float w2 = sb[v][m * 6 + 5];
            s_row[v][m * C_ + c] = w0 * ms[(size_t)i0 * C_ + c]
                                 + w1 * ms[(size_t)i1 * C_ + c]
                                 + w2 * ms[(size_t)i2 * C_ + c];
        }
        if (g4 == 0) s_row[v][2560 + c] = ms[(size_t)n * C_ + c];
    } else {
        for (int i = t; i < 2624; i += 256) s_row[v][i] = 0.f;
    }
    __syncthreads();

    // FFT pass: compute into registers (tasks 0..319 = FFT, 320..383 = center)
    float rg[2][8];
    #pragma unroll
    for (int p = 0; p < 2; p++) {
        int task = t + p * 256;
        if (task < 320) {
            int rho = task >> 6, c = task & 63;
            const float* x = &s_row[v][rho * 512 + c];
            fft8(x[0], x[64], x[128], x[192], x[256], x[320], x[384], x[448], rg[p]);
        } else if (task < 384) {
            rg[p][0] = s_row[v][2560 + (task - 320)];
        }
    }
    __syncthreads();
    #pragma unroll
    for (int p = 0; p < 2; p++) {
        int task = t + p * 256;
        if (task < 320) {
            int rho = task >> 6, c = task & 63;
            int base = rho * 64 + c;
            s_row[v][base]        = rg[p][0];   // Xr0
            s_row[v][320 + base]  = rg[p][1];   // Xr4
            s_row[v][704 + base]  = rg[p][2];   // Xr1
            s_row[v][1024 + base] = rg[p][3];   // Xi1
            s_row[v][1344 + base] = rg[p][4];   // Xr2
            s_row[v][1664 + base] = rg[p][5];   // Xi2
            s_row[v][1984 + base] = rg[p][6];   // Xr3
            s_row[v][2304 + base] = rg[p][7];   // Xi3
        } else if (task < 384) {
            s_row[v][640 + (task - 320)] = rg[p][0];
        }
    }
    __syncthreads();

    // fragment write: 82 chunks x 8 (kk,t4) uint4 per vertex pair
    for (int w = tid; w < CH_N * 8; w += 512) {
        int kt = w >> 3;
        int kk = (w >> 2) & 1;
        int t4 = w & 3;
        int k0 = kt * 32 + kk * 16 + t4 * 2;
        __half2 x = __floats2half2_rn(s_row[0][k0],     s_row[0][k0 + 1]);
        __half2 y = __floats2half2_rn(s_row[1][k0],     s_row[1][k0 + 1]);
        __half2 z = __floats2half2_rn(s_row[0][k0 + 8], s_row[0][k0 + 9]);
        __half2 u = __floats2half2_rn(s_row[1][k0 + 8], s_row[1][k0 + 9]);
        uint4 val;
        val.x = *(uint32_t*)&x; val.y = *(uint32_t*)&y;
        val.z = *(uint32_t*)&z; val.w = *(uint32_t*)&u;
        ((uint4*)(g_Afrag + ((size_t)mb * CH_N + kt) * 4096))
            [(MT * 2 + kk) * 32 + gl * 4 + t4] = val;
    }
}

// ---------------------------------------------------------------------------
// K2: per-frequency fp16 GEMM -> partial products P.
// grid (4 groups, 391 mb). BM=128, BN=128, K=704/640. 8 warps (2m x 4n),
// warp tile 64x32. 4-stage cp.async (16KB/stage).
// ---------------------------------------------------------------------------
__device__ __forceinline__ void mma_f16(float* c, uint32_t a0, uint32_t a1,
                                        uint32_t a2, uint32_t a3,
                                        uint32_t b0, uint32_t b1)
{
    asm volatile(
        "mma.sync.aligned.m16n8k16.row.col.f32.f16.f16.f32 "
        "{%0,%1,%2,%3}, {%4,%5,%6,%7}, {%8,%9}, {%0,%1,%2,%3};\n"
        : "+f"(c[0]), "+f"(c[1]), "+f"(c[2]), "+f"(c[3])
        : "r"(a0), "r"(a1), "r"(a2), "r"(a3), "r"(b0), "r"(b1));
}
__device__ __forceinline__ void cp16(uint32_t s, const void* g) {
    asm volatile("cp.async.cg.shared.global [%0], [%1], 16;" :: "r"(s), "l"(g));
}

#define STAGE_BYTES 16384
#define NSTAGE      4
#define SMEM_TOTAL  (NSTAGE * STAGE_BYTES)   // 64KB

__global__ __launch_bounds__(256, 2)
void gemm_kernel()
{
    extern __shared__ char smem[];
    uint32_t sbase = smem_u32(smem);

    int tid  = threadIdx.x;
    int warp = tid >> 5;
    int ln   = tid & 31;
    int wm   = warp >> 2;          // 0..1
    int wn   = warp & 3;           // 0..3
    int grp  = blockIdx.x;         // 0..3 frequency group
    int mb   = blockIdx.y;

    int cb  = grp_cb(grp);
    int ktn = (grp == 0) ? 22 : 20;

    const uint4* Ag = (const uint4*)(g_Afrag + ((size_t)mb * CH_N + cb) * 4096);
    const uint4* Bg = (const uint4*)(g_Bfrag + (size_t)cb * 4096);

    auto issue = [&](int s) {
        uint32_t dst = sbase + (uint32_t)(s & (NSTAGE - 1)) * STAGE_BYTES;
        const uint4* As = Ag + (size_t)s * 512;
        cp16(dst + tid * 16, As + tid);
        cp16(dst + (tid + 256) * 16, As + tid + 256);
        const uint4* Bs = Bg + (size_t)s * 512;
        cp16(dst + 8192 + tid * 16, Bs + tid);
        cp16(dst + 8192 + (tid + 256) * 16, Bs + tid + 256);
    };

    issue(0);
    asm volatile("cp.async.commit_group;" ::: "memory");
    issue(1);
    asm volatile("cp.async.commit_group;" ::: "memory");
    issue(2);
    asm volatile("cp.async.commit_group;" ::: "memory");

    float acc[4][4][4];
    #pragma unroll
    for (int mt = 0; mt < 4; mt++)
        #pragma unroll
        for (int nt = 0; nt < 4; nt++)
            #pragma unroll
            for (int i = 0; i < 4; i++) acc[mt][nt][i] = 0.f;

    for (int kt = 0; kt < ktn; kt++) {
        asm volatile("cp.async.wait_group 2;" ::: "memory");
        __syncthreads();

        if (kt + 3 < ktn) issue(kt + 3);
        asm volatile("cp.async.commit_group;" ::: "memory");

        uint32_t bufA = sbase + (uint32_t)(kt & (NSTAGE - 1)) * STAGE_BYTES;
        uint32_t bufB = bufA + 8192;

        #pragma unroll
        for (int kk = 0; kk < 2; kk++) {
            uint4 af[4];
            uint2 bf[4];
            #pragma unroll
            for (int mt = 0; mt < 4; mt++) {
                uint32_t a = bufA + ((((wm * 4 + mt) * 2 + kk) * 32 + ln) * 16);
                asm volatile("ld.shared.v4.b32 {%0,%1,%2,%3}, [%4];"
                             : "=r"(af[mt].x), "=r"(af[mt].y), "=r"(af[mt].z), "=r"(af[mt].w)
                             : "r"(a));
            }
            #pragma unroll
            for (int nt = 0; nt < 4; nt++) {
                int NT = wn * 4 + nt;
                uint32_t b = bufB + (((NT * 2 + kk) * 32 + ln) * 8);
                asm volatile("ld.shared.v2.b32 {%0,%1}, [%2];"
                             : "=r"(bf[nt].x), "=r"(bf[nt].y) : "r"(b));
            }
            #pragma unroll
            for (int mt = 0; mt < 4; mt++)
                #pragma unroll
                for (int nt = 0; nt < 4; nt++)
                    mma_f16(acc[mt][nt], af[mt].x, af[mt].y, af[mt].z, af[mt].w,
                            bf[nt].x, bf[nt].y);
        }
    }

    // write partial products P
    int g_  = ln >> 2;
    int t4  = ln & 3;
    #pragma unroll
    for (int nt = 0; nt < 4; nt++) {
        int col = grp * 128 + wn * 32 + nt * 8 + t4 * 2;
        #pragma unroll
        for (int mt = 0; mt < 4; mt++) {
            int row0 = mb * 128 + wm * 64 + mt * 16 + g_;
            if (row0 < N_V)
                *(float2*)(g_P + (size_t)row0 * 512 + col) =
                    make_float2(acc[mt][nt][0], acc[mt][nt][1]);
            if (row0 + 8 < N_V)
                *(float2*)(g_P + (size_t)(row0 + 8) * 512 + col) =
                    make_float2(acc[mt][nt][2], acc[mt][nt][3]);
        }
    }
}

// ---------------------------------------------------------------------------
// K3: inverse angular DFT combine + bias + relu.
// out[n, o*64+t] = relu( (P0 + (-1)^o P4 + 2*sum_f Rf*cos - If*sin)/8 + bias )
// ---------------------------------------------------------------------------
__global__ __launch_bounds__(256)
void combine_kernel(const float* __restrict__ bias, float* __restrict__ out)
{
    int gidx = blockIdx.x * 256 + threadIdx.x;
    int n = gidx >> 6;
    int t = gidx & 63;
    if (n >= N_V) return;

    const float* P = g_P + (size_t)n * 512;
    float P0 = P[t],        P4 = P[64 + t];
    float R1 = P[128 + t],  I1 = P[192 + t];
    float R2 = P[256 + t],  I2 = P[320 + t];
    float R3 = P[384 + t],  I3 = P[448 + t];
    float b = bias[t];

    const float CO1[8] = {1.f, SQ2, 0.f, -SQ2, -1.f, -SQ2, 0.f, SQ2};
    const float SI1[8] = {0.f, SQ2, 1.f, SQ2, 0.f, -SQ2, -1.f, -SQ2};
    const float CO2[8] = {1.f, 0.f, -1.f, 0.f, 1.f, 0.f, -1.f, 0.f};
    const float SI2[8] = {0.f, 1.f, 0.f, -1.f, 0.f, 1.f, 0.f, -1.f};
    const float CO3[8] = {1.f, -SQ2, 0.f, SQ2, -1.f, SQ2, 0.f, -SQ2};
    const float SI3[8] = {0.f, SQ2, -1.f, SQ2, 0.f, -SQ2, 1.f, -SQ2};

    float* orow = out + (size_t)n * NCOL;
    #pragma unroll
    for (int o = 0; o < 8; o++) {
        float sgn = (o & 1) ? -1.f : 1.f;
        float val = 0.125f * (P0 + sgn * P4
                    + 2.f * (R1 * CO1[o] - I1 * SI1[o]
                           + R2 * CO2[o] - I2 * SI2[o]
                           + R3 * CO3[o] - I3 * SI3[o])) + b;
        orow[o * 64 + t] = val > 0.f ? val : 0.f;
    }
}

// ---------------------------------------------------------------------------
// Launch. Order: dummy, build_V, build_X, gemm, combine
// (gemm = our 4th launch = global launch #5 -> captured by ncu -s 5 -c 1).
// Inputs: mesh_signal, bary_coordinates, neighbor_weights, center_weights,
//         bias, interp_coeff
// ---------------------------------------------------------------------------
extern "C" void kernel_launch(void* const* d_in, const int* in_sizes, int n_in,
                              void* d_out, int out_size)
{
    const float* ms    = (const float*)d_in[0];
    const float* bary  = (const float*)d_in[1];
    const float* nw    = (const float*)d_in[2];
    const float* cw    = (const float*)d_in[3];
    const float* bias  = (const float*)d_in[4];
    const float* coeff = (const float*)d_in[5];
    float* out = (float*)d_out;

    cudaFuncSetAttribute(gemm_kernel,
                         cudaFuncAttributeMaxDynamicSharedMemorySize, SMEM_TOTAL);

    dummy_kernel<<<1, 1>>>();
    build_V_kernel<<<64, 64>>>(nw, cw, coeff);
    build_X_kernel<<<MB_N * 64, 512>>>(ms, bary);

    dim3 grid(4, MB_N);
    gemm_kernel<<<grid, 256, SMEM_TOTAL>>>();

    combine_kernel<<<(N_V * 64 + 255) / 256, 256>>>(bias, out);
}

// round 11
// speedup vs baseline: 2.9028x; 1.1413x over previous
#include <cuda_runtime.h>
#include <cuda_fp16.h>
#include <cstdint>

// Problem constants
#define N_V   50000
#define R_    5
#define A_    8
#define RA    40
#define C_    64
#define NCOL  512
#define CH_N  82              // 32-k chunks total: g0:22 (K=704), g1-3:20 (K=640)
#define MB_N  391             // ceil(50048/128)
#define SQ2   0.70710678118654752f

// Scratch (static device arrays — no cudaMalloc allowed)
__device__ __half g_msh[(size_t)N_V * C_];               // 6.4 MB fp16 mesh signal
__device__ __half g_Afrag[(size_t)MB_N * CH_N * 4096];   // ~262 MB freq-domain A frags
__device__ __half g_Bfrag[(size_t)CH_N * 4096];          // 672 KB freq-domain B frags
__device__ float  g_P[(size_t)MB_N * 128 * 512];         // ~102 MB partial products

__device__ __forceinline__ uint32_t smem_u32(const void* p) {
    uint32_t a;
    asm("{ .reg .u64 t; cvta.to.shared.u64 t, %1; cvt.u32.u64 %0, t; }" : "=r"(a) : "l"(p));
    return a;
}
__device__ __forceinline__ int grp_cb(int g) { return g == 0 ? 0 : 2 + g * 20; }

// K-pre: fp32 -> fp16 mesh signal (also serves as ncu launch-offset shim).
__global__ void convert_ms_kernel(const float* __restrict__ ms)
{
    int i = blockIdx.x * 256 + threadIdx.x;      // half2 index
    if (i < N_V * 32) {
        float2 v = ((const float2*)ms)[i];
        ((__half2*)g_msh)[i] = __floats2half2_rn(v.x, v.y);
    }
}

// 8-point real FFT, e^{-i2*pi*f*a/8} convention. out: r0,r4,r1,i1,r2,i2,r3,i3
__device__ __forceinline__ void fft8(float x0, float x1, float x2, float x3,
                                     float x4, float x5, float x6, float x7,
                                     float* o)
{
    float a04 = x0 + x4, s04 = x0 - x4;
    float a26 = x2 + x6, s26 = x2 - x6;
    float a15 = x1 + x5, s15 = x1 - x5;
    float a37 = x3 + x7, s37 = x3 - x7;
    o[0] = a04 + a26 + a15 + a37;          // r0
    o[1] = a04 + a26 - a15 - a37;          // r4
    float u = SQ2 * (s15 - s37);
    float w = SQ2 * (s15 + s37);
    o[2] = s04 + u;                        // r1
    o[3] = -(w + s26);                     // i1
    o[4] = a04 - a26;                      // r2
    o[5] = -(a15 - a37);                   // i2
    o[6] = s04 - u;                        // r3
    o[7] = -(w - s26);                     // i3
}

// B fragment half index: group chunk base cb, k within group panel, col j in [0,128)
__device__ __forceinline__ size_t bfrag_idx(int cb, int klocal, int j) {
    int kt = klocal >> 5, kl = klocal & 31;
    int kk = kl >> 4, kb = kl & 15;
    int r = kb >> 3, rem = kb & 7, t4 = rem >> 1, e = rem & 1;
    int NT = j >> 3, gn = j & 7;
    int ln = gn * 4 + t4;
    return (size_t)(cb + kt) * 4096 + (size_t)(((NT * 2 + kk) * 32 + ln) * 4 + r * 2 + e);
}

// ---------------------------------------------------------------------------
// K0: fold prior into V (= Weff at o=0), rFFT over alpha, write B fragments.
// ---------------------------------------------------------------------------
__global__ void build_V_kernel(const float* __restrict__ nw,
                               const float* __restrict__ cw,
                               const float* __restrict__ coeff)
{
    int t = blockIdx.x;            // 0..63 template
    int c = threadIdx.x;           // 0..63 channel

    __shared__ float s_coeff[R_ * A_ * RA];
    for (int i = c; i < R_ * A_ * RA; i += 64) s_coeff[i] = coeff[i];
    __syncthreads();

    float wv[R_][A_];
    #pragma unroll
    for (int r = 0; r < R_; r++)
        #pragma unroll
        for (int a = 0; a < A_; a++)
            wv[r][a] = nw[(((size_t)t * R_ + r) * A_ + a) * C_ + c];

    float v[RA];
    for (int m = 0; m < RA; m++) {
        float acc = 0.f;
        #pragma unroll
        for (int r = 0; r < R_; r++)
            #pragma unroll
            for (int a = 0; a < A_; a++)
                acc += s_coeff[(r * A_ + a) * RA + m] * wv[r][a];
        v[m] = acc;
    }

    #pragma unroll
    for (int rho = 0; rho < R_; rho++) {
        float o[8];
        fft8(v[rho * 8 + 0], v[rho * 8 + 1], v[rho * 8 + 2], v[rho * 8 + 3],
             v[rho * 8 + 4], v[rho * 8 + 5], v[rho * 8 + 6], v[rho * 8 + 7], o);
        int kb = rho * 64 + c;
        __half zero = __float2half_rn(0.f);
        g_Bfrag[bfrag_idx(0, kb,       t     )] = __float2half_rn(o[0]);
        g_Bfrag[bfrag_idx(0, 320 + kb, t     )] = zero;
        g_Bfrag[bfrag_idx(0, kb,       64 + t)] = zero;
        g_Bfrag[bfrag_idx(0, 320 + kb, 64 + t)] = __float2half_rn(o[1]);
        #pragma unroll
        for (int f = 1; f <= 3; f++) {
            float vr = o[f * 2], vi = o[f * 2 + 1];
            int cb = grp_cb(f);
            g_Bfrag[bfrag_idx(cb, kb,       t     )] = __float2half_rn(vr);
            g_Bfrag[bfrag_idx(cb, 320 + kb, t     )] = __float2half_rn(vi);
            g_Bfrag[bfrag_idx(cb, kb,       64 + t)] = __float2half_rn(vi);
            g_Bfrag[bfrag_idx(cb, 320 + kb, 64 + t)] = __float2half_rn(-vr);
        }
    }
    g_Bfrag[bfrag_idx(0, 640 + c, t     )] = __float2half_rn(8.f * cw[t * C_ + c]);
    g_Bfrag[bfrag_idx(0, 640 + c, 64 + t)] = __float2half_rn(0.f);
}

// ---------------------------------------------------------------------------
// K1: fp16 barycentric gather -> angular rFFT -> fp16 A-fragments.
// One block per vertex PAIR (n, n+8), 512 threads (bit 8 = vertex).
// Gather: 256 threads/vertex = 8 m-groups x 32 channel-pairs, half2 loads.
// ---------------------------------------------------------------------------
__global__ __launch_bounds__(512)
void build_X_kernel(const float* __restrict__ bary)
{
    int bp = blockIdx.x;
    int mb = bp >> 6;
    int q  = bp & 63;
    int MT = q >> 3;
    int gl = q & 7;
    int n0 = mb * 128 + MT * 16 + gl;

    __shared__ float s_row[2][2624];
    __shared__ float sb[2][240];
    int tid = threadIdx.x;
    int v   = tid >> 8;
    int t   = tid & 255;
    int n   = n0 + 8 * v;

    if (t < 240) sb[v][t] = (n < N_V) ? bary[(size_t)n * 240 + t] : 0.f;
    __syncthreads();

    if (n < N_V) {
        int g8 = t >> 5;            // 0..7 m-group
        int cp = t & 31;            // channel pair 0..31
        const __half2* msh2 = (const __half2*)g_msh;
        #pragma unroll
        for (int it = 0; it < 5; it++) {
            int m  = it * 8 + g8;
            int i0 = (int)sb[v][m * 6 + 0]; float w0 = sb[v][m * 6 + 1];
            int i1 = (int)sb[v][m * 6 + 2]; float w1 = sb[v][m * 6 + 3];
            int i2 = (int)sb[v][m * 6 + 4]; float w2 = sb[v][m * 6 + 5];
            float2 x0 = __half22float2(msh2[(size_t)i0 * 32 + cp]);
            float2 x1 = __half22float2(msh2[(size_t)i1 * 32 + cp]);
            float2 x2 = __half22float2(msh2[(size_t)i2 * 32 + cp]);
            float2 r;
            r.x = w0 * x0.x + w1 * x1.x + w2 * x2.x;
            r.y = w0 * x0.y + w1 * x1.y + w2 * x2.y;
            *(float2*)&s_row[v][m * C_ + cp * 2] = r;
        }
        if (g8 == 0) {
            float2 cme = __half22float2(msh2[(size_t)n * 32 + cp]);
            *(float2*)&s_row[v][2560 + cp * 2] = cme;
        }
    } else {
        for (int i = t; i < 2624; i += 256) s_row[v][i] = 0.f;
    }
    __syncthreads();

    // FFT pass (tasks 0..319 = FFT over alpha; center rows already placed)
    float rg[2][8];
    #pragma unroll
    for (int p = 0; p < 2; p++) {
        int task = t + p * 256;
        if (task < 320) {
            int rho = task >> 6, c = task & 63;
            const float* x = &s_row[v][rho * 512 + c];
            fft8(x[0], x[64], x[128], x[192], x[256], x[320], x[384], x[448], rg[p]);
        } else if (task < 384) {
            rg[p][0] = s_row[v][2560 + (task - 320)];
        }
    }
    __syncthreads();
    #pragma unroll
    for (int p = 0; p < 2; p++) {
        int task = t + p * 256;
        if (task < 320) {
            int rho = task >> 6, c = task & 63;
            int base = rho * 64 + c;
            s_row[v][base]        = rg[p][0];   // Xr0
            s_row[v][320 + base]  = rg[p][1];   // Xr4
            s_row[v][704 + base]  = rg[p][2];   // Xr1
            s_row[v][1024 + base] = rg[p][3];   // Xi1
            s_row[v][1344 + base] = rg[p][4];   // Xr2
            s_row[v][1664 + base] = rg[p][5];   // Xi2
            s_row[v][1984 + base] = rg[p][6];   // Xr3
            s_row[v][2304 + base] = rg[p][7];   // Xi3
        } else if (task < 384) {
            s_row[v][640 + (task - 320)] = rg[p][0];
        }
    }
    __syncthreads();

    // fragment write: 82 chunks x 8 (kk,t4) uint4 per vertex pair
    for (int w = tid; w < CH_N * 8; w += 512) {
        int kt = w >> 3;
        int kk = (w >> 2) & 1;
        int t4 = w & 3;
        int k0 = kt * 32 + kk * 16 + t4 * 2;
        __half2 x = __floats2half2_rn(s_row[0][k0],     s_row[0][k0 + 1]);
        __half2 y = __floats2half2_rn(s_row[1][k0],     s_row[1][k0 + 1]);
        __half2 z = __floats2half2_rn(s_row[0][k0 + 8], s_row[0][k0 + 9]);
        __half2 u = __floats2half2_rn(s_row[1][k0 + 8], s_row[1][k0 + 9]);
        uint4 val;
        val.x = *(uint32_t*)&x; val.y = *(uint32_t*)&y;
        val.z = *(uint32_t*)&z; val.w = *(uint32_t*)&u;
        ((uint4*)(g_Afrag + ((size_t)mb * CH_N + kt) * 4096))
            [(MT * 2 + kk) * 32 + gl * 4 + t4] = val;
    }
}

// ---------------------------------------------------------------------------
// K2: per-frequency fp16 GEMM -> partial products P.
// grid (4 groups, 391 mb). BM=128, BN=128, 8 warps (2m x 4n), warp tile 64x32.
// 4-stage cp.async (16KB/stage).
// ---------------------------------------------------------------------------
__device__ __forceinline__ void mma_f16(float* c, uint32_t a0, uint32_t a1,
                                        uint32_t a2, uint32_t a3,
                                        uint32_t b0, uint32_t b1)
{
    asm volatile(
        "mma.sync.aligned.m16n8k16.row.col.f32.f16.f16.f32 "
        "{%0,%1,%2,%3}, {%4,%5,%6,%7}, {%8,%9}, {%0,%1,%2,%3};\n"
        : "+f"(c[0]), "+f"(c[1]), "+f"(c[2]), "+f"(c[3])
        : "r"(a0), "r"(a1), "r"(a2), "r"(a3), "r"(b0), "r"(b1));
}
__device__ __forceinline__ void cp16(uint32_t s, const void* g) {
    asm volatile("cp.async.cg.shared.global [%0], [%1], 16;" :: "r"(s), "l"(g));
}

#define STAGE_BYTES 16384
#define NSTAGE      4
#define SMEM_TOTAL  (NSTAGE * STAGE_BYTES)   // 64KB

__global__ __launch_bounds__(256, 2)
void gemm_kernel()
{
    extern __shared__ char smem[];
    uint32_t sbase = smem_u32(smem);

    int tid  = threadIdx.x;
    int warp = tid >> 5;
    int ln   = tid & 31;
    int wm   = warp >> 2;          // 0..1
    int wn   = warp & 3;           // 0..3
    int grp  = blockIdx.x;         // 0..3 frequency group
    int mb   = blockIdx.y;

    int cb  = grp_cb(grp);
    int ktn = (grp == 0) ? 22 : 20;

    const uint4* Ag = (const uint4*)(g_Afrag + ((size_t)mb * CH_N + cb) * 4096);
    const uint4* Bg = (const uint4*)(g_Bfrag + (size_t)cb * 4096);

    auto issue = [&](int s) {
        uint32_t dst = sbase + (uint32_t)(s & (NSTAGE - 1)) * STAGE_BYTES;
        const uint4* As = Ag + (size_t)s * 512;
        cp16(dst + tid * 16, As + tid);
        cp16(dst + (tid + 256) * 16, As + tid + 256);
        const uint4* Bs = Bg + (size_t)s * 512;
        cp16(dst + 8192 + tid * 16, Bs + tid);
        cp16(dst + 8192 + (tid + 256) * 16, Bs + tid + 256);
    };

    issue(0);
    asm volatile("cp.async.commit_group;" ::: "memory");
    issue(1);
    asm volatile("cp.async.commit_group;" ::: "memory");
    issue(2);
    asm volatile("cp.async.commit_group;" ::: "memory");

    float acc[4][4][4];
    #pragma unroll
    for (int mt = 0; mt < 4; mt++)
        #pragma unroll
        for (int nt = 0; nt < 4; nt++)
            #pragma unroll
            for (int i = 0; i < 4; i++) acc[mt][nt][i] = 0.f;

    for (int kt = 0; kt < ktn; kt++) {
        asm volatile("cp.async.wait_group 2;" ::: "memory");
        __syncthreads();

        if (kt + 3 < ktn) issue(kt + 3);
        asm volatile("cp.async.commit_group;" ::: "memory");

        uint32_t bufA = sbase + (uint32_t)(kt & (NSTAGE - 1)) * STAGE_BYTES;
        uint32_t bufB = bufA + 8192;

        #pragma unroll
        for (int kk = 0; kk < 2; kk++) {
            uint4 af[4];
            uint2 bf[4];
            #pragma unroll
            for (int mt = 0; mt < 4; mt++) {
                uint32_t a = bufA + ((((wm * 4 + mt) * 2 + kk) * 32 + ln) * 16);
                asm volatile("ld.shared.v4.b32 {%0,%1,%2,%3}, [%4];"
                             : "=r"(af[mt].x), "=r"(af[mt].y), "=r"(af[mt].z), "=r"(af[mt].w)
                             : "r"(a));
            }
            #pragma unroll
            for (int nt = 0; nt < 4; nt++) {
                int NT = wn * 4 + nt;
                uint32_t b = bufB + (((NT * 2 + kk) * 32 + ln) * 8);
                asm volatile("ld.shared.v2.b32 {%0,%1}, [%2];"
                             : "=r"(bf[nt].x), "=r"(bf[nt].y) : "r"(b));
            }
            #pragma unroll
            for (int mt = 0; mt < 4; mt++)
                #pragma unroll
                for (int nt = 0; nt < 4; nt++)
                    mma_f16(acc[mt][nt], af[mt].x, af[mt].y, af[mt].z, af[mt].w,
                            bf[nt].x, bf[nt].y);
        }
    }

    // write partial products P
    int g_  = ln >> 2;
    int t4  = ln & 3;
    #pragma unroll
    for (int nt = 0; nt < 4; nt++) {
        int col = grp * 128 + wn * 32 + nt * 8 + t4 * 2;
        #pragma unroll
        for (int mt = 0; mt < 4; mt++) {
            int row0 = mb * 128 + wm * 64 + mt * 16 + g_;
            if (row0 < N_V)
                *(float2*)(g_P + (size_t)row0 * 512 + col) =
                    make_float2(acc[mt][nt][0], acc[mt][nt][1]);
            if (row0 + 8 < N_V)
                *(float2*)(g_P + (size_t)(row0 + 8) * 512 + col) =
                    make_float2(acc[mt][nt][2], acc[mt][nt][3]);
        }
    }
}

// ---------------------------------------------------------------------------
// K3: inverse angular DFT combine + bias + relu.
// ---------------------------------------------------------------------------
__global__ __launch_bounds__(256)
void combine_kernel(const float* __restrict__ bias, float* __restrict__ out)
{
    int gidx = blockIdx.x * 256 + threadIdx.x;
    int n = gidx >> 6;
    int t = gidx & 63;
    if (n >= N_V) return;

    const float* P = g_P + (size_t)n * 512;
    float P0 = P[t],        P4 = P[64 + t];
    float R1 = P[128 + t],  I1 = P[192 + t];
    float R2 = P[256 + t],  I2 = P[320 + t];
    float R3 = P[384 + t],  I3 = P[448 + t];
    float b = bias[t];

    const float CO1[8] = {1.f, SQ2, 0.f, -SQ2, -1.f, -SQ2, 0.f, SQ2};
    const float SI1[8] = {0.f, SQ2, 1.f, SQ2, 0.f, -SQ2, -1.f, -SQ2};
    const float CO2[8] = {1.f, 0.f, -1.f, 0.f, 1.f, 0.f, -1.f, 0.f};
    const float SI2[8] = {0.f, 1.f, 0.f, -1.f, 0.f, 1.f, 0.f, -1.f};
    const float CO3[8] = {1.f, -SQ2, 0.f, SQ2, -1.f, SQ2, 0.f, -SQ2};
    const float SI3[8] = {0.f, SQ2, -1.f, SQ2, 0.f, -SQ2, 1.f, -SQ2};

    float* orow = out + (size_t)n * NCOL;
    #pragma unroll
    for (int o = 0; o < 8; o++) {
        float sgn = (o & 1) ? -1.f : 1.f;
        float val = 0.125f * (P0 + sgn * P4
                    + 2.f * (R1 * CO1[o] - I1 * SI1[o]
                           + R2 * CO2[o] - I2 * SI2[o]
                           + R3 * CO3[o] - I3 * SI3[o])) + b;
        orow[o * 64 + t] = val > 0.f ? val : 0.f;
    }
}

// ---------------------------------------------------------------------------
// Launch order: convert, build_V, build_X, gemm, combine
// (gemm = our 4th launch -> ncu -s 5 -c 1 captures it).
// Inputs: mesh_signal, bary_coordinates, neighbor_weights, center_weights,
//         bias, interp_coeff
// ---------------------------------------------------------------------------
extern "C" void kernel_launch(void* const* d_in, const int* in_sizes, int n_in,
                              void* d_out, int out_size)
{
    const float* ms    = (const float*)d_in[0];
    const float* bary  = (const float*)d_in[1];
    const float* nw    = (const float*)d_in[2];
    const float* cw    = (const float*)d_in[3];
    const float* bias  = (const float*)d_in[4];
    const float* coeff = (const float*)d_in[5];
    float* out = (float*)d_out;

    cudaFuncSetAttribute(gemm_kernel,
                         cudaFuncAttributeMaxDynamicSharedMemorySize, SMEM_TOTAL);

    convert_ms_kernel<<<(N_V * 32 + 255) / 256, 256>>>(ms);
    build_V_kernel<<<64, 64>>>(nw, cw, coeff);
    build_X_kernel<<<MB_N * 64, 512>>>(bary);

    dim3 grid(4, MB_N);
    gemm_kernel<<<grid, 256, SMEM_TOTAL>>>();

    combine_kernel<<<(N_V * 64 + 255) / 256, 256>>>(bias, out);
}